// round 7
// baseline (speedup 1.0000x reference)
#include <cuda_runtime.h>
#include <cuda_bf16.h>
#include <cstdint>

// ---------------------------------------------------------------------------
// octree_level — replicating the reference AS EXECUTED (jax x64 disabled:
// int64 keys silently wrap to int32).
//
// Wrapped key <-> (x mod 256, y, z). Therefore:
//   parent class    c = (px mod 256, py, pz),  px = x>>1
//   negative classes (cmod >= 128) -> valid=False -> (-1,-1,-1) rows at FRONT
//   positive classes (cmod < 128)  -> coord rows sorted lex (cmod,py,pz)
//   occupancy(child) = exists leaf with (x mod 256, y, z) == child
//     (child keys for pxm>=64 re-wrap negative, but match the wrapped leaf
//      keys value-exactly, so plain wrapped-set membership is still right)
//
// Bitmaps:
//   g_childbm : bit (pmp<<3)|o, pmp = ((x&255)>>1)<<18 | (y>>1)<<9 | (z>>1)
//               -> 2^28 bits (32 MB); byte pmp IS the occupancy row
//   g_parbm   : bit pcls = ((x>>1)&255)<<18 | (y>>1)<<9 | (z>>1)
//               -> 2^26 bits (8 MB); lower half = valid classes, upper = neg
// ---------------------------------------------------------------------------

#define NCW (1u << 23)   // child bitmap words (2^28 bits = 32 MB)
#define NPW (1u << 21)   // parent bitmap words (2^26 bits = 8 MB)
#define CBLK 512         // count blocks (cover all NPW words)
#define EBLK 256         // emit blocks (lower half only)
#define TPB  256
#define WPT  16          // words per thread: CBLK*TPB*WPT = 2^21 = NPW

__device__ unsigned int g_childbm[NCW];
__device__ unsigned int g_parbm[NPW];
__device__ unsigned int g_bsum[CBLK];
__device__ unsigned int g_boff[EBLK];
__device__ unsigned int g_nneg;
__device__ unsigned int g_nend;

// ---- clear both bitmaps ----
__global__ void k_clear() {
    unsigned idx    = blockIdx.x * blockDim.x + threadIdx.x;
    unsigned stride = gridDim.x * blockDim.x;
    uint4 z = make_uint4(0u, 0u, 0u, 0u);
    uint4* c4 = reinterpret_cast<uint4*>(g_childbm);
    for (unsigned i = idx; i < NCW / 4; i += stride) c4[i] = z;
    uint4* p4 = reinterpret_cast<uint4*>(g_parbm);
    for (unsigned i = idx; i < NPW / 4; i += stride) p4[i] = z;
}

// ---- scatter leaves ----
__global__ void k_scatter(const float* __restrict__ leaf, int n) {
    int i = blockIdx.x * blockDim.x + threadIdx.x;
    if (i >= n) return;
    int x = (int)floorf(leaf[3 * i + 0]);
    int y = (int)floorf(leaf[3 * i + 1]);
    int z = (int)floorf(leaf[3 * i + 2]);
    // parent class (9-bit x-field holds px mod 256)
    unsigned pcls = (((unsigned)(x >> 1) & 255u) << 18)
                  | ((unsigned)(y >> 1) << 9) | (unsigned)(z >> 1);
    atomicOr(&g_parbm[pcls >> 5], 1u << (pcls & 31));
    // wrapped child cell, parent-major packing
    unsigned pmp = ((((unsigned)x & 255u) >> 1) << 18)
                 | ((unsigned)(y >> 1) << 9) | (unsigned)(z >> 1);
    unsigned o = ((unsigned)(x & 1) << 2) | ((unsigned)(y & 1) << 1) | (unsigned)(z & 1);
    unsigned bit = (pmp << 3) | o;                 // < 2^28
    atomicOr(&g_childbm[bit >> 5], 1u << (bit & 31));
}

// ---- pass 1: per-block popcount of parent-class bitmap ----
__global__ void k_count() {
    __shared__ unsigned s[TPB];
    unsigned base = blockIdx.x * (TPB * WPT) + threadIdx.x * WPT;
    const uint4* w4 = reinterpret_cast<const uint4*>(g_parbm + base);
    unsigned c = 0;
#pragma unroll
    for (int v = 0; v < WPT / 4; v++) {
        uint4 a = w4[v];
        c += __popc(a.x) + __popc(a.y) + __popc(a.z) + __popc(a.w);
    }
    s[threadIdx.x] = c;
    __syncthreads();
    for (int off = TPB / 2; off > 0; off >>= 1) {
        if (threadIdx.x < off) s[threadIdx.x] += s[threadIdx.x + off];
        __syncthreads();
    }
    if (threadIdx.x == 0) g_bsum[blockIdx.x] = s[0];
}

// ---- scan: Nneg = sum upper blocks; prefix over lower blocks, base Nneg ----
__global__ void k_scan() {       // 512 threads
    __shared__ unsigned slo[EBLK];
    __shared__ unsigned sup[EBLK];
    __shared__ unsigned nneg_sh;
    int t = threadIdx.x;
    unsigned v = g_bsum[t];
    if (t >= EBLK) sup[t - EBLK] = v;
    __syncthreads();
    for (int off = EBLK / 2; off > 0; off >>= 1) {
        if (t < off) sup[t] += sup[t + off];
        __syncthreads();
    }
    if (t == 0) { nneg_sh = sup[0]; g_nneg = sup[0]; }
    __syncthreads();
    unsigned nneg = nneg_sh;
    if (t < EBLK) slo[t] = v;
    __syncthreads();
    for (int off = 1; off < EBLK; off <<= 1) {
        unsigned u = 0;
        if (t < EBLK && t >= off) u = slo[t - off];
        __syncthreads();
        if (t < EBLK) slo[t] += u;
        __syncthreads();
    }
    if (t < EBLK) g_boff[t] = nneg + slo[t] - v;   // exclusive + front offset
    if (t == EBLK - 1) g_nend = nneg + slo[EBLK - 1];
}

// ---- fill sentinel rows: [0, Nneg) and [Nend, n) ----
__global__ void k_fill(float* __restrict__ outPC, float* __restrict__ outOcc, int n) {
    int r = blockIdx.x * blockDim.x + threadIdx.x;
    if (r >= n) return;
    if ((unsigned)r >= g_nneg && (unsigned)r < g_nend) return;
    outPC[3 * r + 0] = -1.0f;
    outPC[3 * r + 1] = -1.0f;
    outPC[3 * r + 2] = -1.0f;
    float4 z4 = make_float4(0.f, 0.f, 0.f, 0.f);
    float4* occ4 = reinterpret_cast<float4*>(outOcc + 8 * (size_t)r);
    occ4[0] = z4;
    occ4[1] = z4;
}

// ---- pass 2: enumerate lower-half parent classes, emit coords + occupancy ----
__global__ void k_emit(float* __restrict__ outPC, float* __restrict__ outOcc) {
    __shared__ unsigned s[TPB];
    int t = threadIdx.x;
    unsigned base = blockIdx.x * (TPB * WPT) + t * WPT;   // words in lower half
    unsigned words[WPT];
    const uint4* w4 = reinterpret_cast<const uint4*>(g_parbm + base);
    unsigned c = 0;
#pragma unroll
    for (int v = 0; v < WPT / 4; v++) {
        uint4 a = w4[v];
        words[4 * v + 0] = a.x;
        words[4 * v + 1] = a.y;
        words[4 * v + 2] = a.z;
        words[4 * v + 3] = a.w;
        c += __popc(a.x) + __popc(a.y) + __popc(a.z) + __popc(a.w);
    }
    s[t] = c;
    __syncthreads();
    for (int off = 1; off < TPB; off <<= 1) {
        unsigned u = (t >= off) ? s[t - off] : 0u;
        __syncthreads();
        s[t] += u;
        __syncthreads();
    }
    unsigned pos = g_boff[blockIdx.x] + (s[t] - c);   // global output row

#pragma unroll
    for (int w = 0; w < WPT; w++) {
        unsigned word = words[w];
        unsigned wi = base + w;
        while (word) {
            int b = __ffs(word) - 1;
            word &= word - 1;
            unsigned p = wi * 32u + (unsigned)b;      // class, p < 2^25
            outPC[3 * pos + 0] = (float)(p >> 18);          // px mod 256, < 128
            outPC[3 * pos + 1] = (float)((p >> 9) & 511u);  // py
            outPC[3 * pos + 2] = (float)(p & 511u);         // pz
            unsigned mask = (__ldg(&g_childbm[p >> 2]) >> ((p & 3u) * 8u)) & 0xFFu;
            float4 lo, hi;
            lo.x = (float)( mask       & 1u);
            lo.y = (float)((mask >> 1) & 1u);
            lo.z = (float)((mask >> 2) & 1u);
            lo.w = (float)((mask >> 3) & 1u);
            hi.x = (float)((mask >> 4) & 1u);
            hi.y = (float)((mask >> 5) & 1u);
            hi.z = (float)((mask >> 6) & 1u);
            hi.w = (float)((mask >> 7) & 1u);
            float4* occ4 = reinterpret_cast<float4*>(outOcc + 8 * (size_t)pos);
            occ4[0] = lo;
            occ4[1] = hi;
            pos++;
        }
    }
}

extern "C" void kernel_launch(void* const* d_in, const int* in_sizes, int n_in,
                              void* d_out, int out_size) {
    const float* leaf = (const float*)d_in[0];
    int n = in_sizes[0] / 3;
    float* out    = (float*)d_out;
    float* outPC  = out;                      // [n,3] parent coords (wrapped semantics)
    float* outOcc = out + (size_t)n * 3;      // [n,8] occupancy

    k_clear  <<<2048, 256>>>();
    k_scatter<<<(n + 255) / 256, 256>>>(leaf, n);
    k_count  <<<CBLK, TPB>>>();
    k_scan   <<<1, 2 * EBLK>>>();
    k_fill   <<<(n + 255) / 256, 256>>>(outPC, outOcc, n);
    k_emit   <<<EBLK, TPB>>>(outPC, outOcc);
}